// round 5
// baseline (speedup 1.0000x reference)
#include <cuda_runtime.h>
#include <cuda_bf16.h>
#include <cstdint>
#include <cstddef>

#define T_LEN 4096
#define EMBD  300
#define HID   512
#define KTAG  20
#define START_TAG 18
#define STOP_TAG  19
#define NEGV  (-10000.0f)
#define CHUNK 16
#define NCHUNK (T_LEN / CHUNK)   // 256

// ---------------- scratch (static device globals; no allocation) ----------------
__device__ float              g_xproj[2][T_LEN][4 * HID];  // 64 MB
__device__ float              g_hs[2][T_LEN][HID];         // 16 MB
__device__ float              g_feats[T_LEN][KTAG];
__device__ unsigned long long g_hpair[2][2][HID];          // [dir][parity][h]: {tag|bits}
__device__ float              g_tree[2][NCHUNK][KTAG][KTAG];

__device__ __forceinline__ unsigned long long packhf(unsigned tag, float v) {
    return ((unsigned long long)tag << 32) | (unsigned long long)__float_as_uint(v);
}
__device__ __forceinline__ float tanh_fast(float x) {
    return 1.f - 2.f / (__expf(2.f * x) + 1.f);
}
__device__ __forceinline__ float sigm_fast(float x) {
    return 1.f / (1.f + __expf(-x));
}

#define LD2_RELAXED(a, b, p)                                              \
    asm volatile("ld.relaxed.gpu.global.v2.u64 {%0,%1}, [%2];"            \
                 : "=l"(a), "=l"(b) : "l"(p) : "memory")

#define FMA_F32X2(acc, x, y)                                              \
    asm("fma.rn.f32x2 %0, %1, %2, %0;" : "+l"(acc) : "l"(x), "l"(y))

// ---------------- init: seed h0 pairs (tag 0), poison other parity ----------------
__global__ void init_kernel(const float* __restrict__ h0) {
    int tid = threadIdx.x;                // 1024 threads
    int dir = tid >> 9, i = tid & 511;
    g_hpair[dir][0][i] = packhf(0u, h0[dir * HID + i]);
    g_hpair[dir][1][i] = packhf(0x7fffffffu, 0.f);
}

// ---------------- K1: x_proj = emb(gather) @ w_ih^T + b_ih + b_hh ----------------
__global__ __launch_bounds__(256) void xproj_kernel(
    const int*   __restrict__ sentence,
    const float* __restrict__ embed,
    const float* __restrict__ w_ih_f, const float* __restrict__ b_ih_f, const float* __restrict__ b_hh_f,
    const float* __restrict__ w_ih_b, const float* __restrict__ b_ih_b, const float* __restrict__ b_hh_b)
{
    const int dir = blockIdx.z;
    const float* __restrict__ w_ih = dir ? w_ih_b : w_ih_f;
    const float* __restrict__ bi   = dir ? b_ih_b : b_ih_f;
    const float* __restrict__ bh   = dir ? b_hh_b : b_hh_f;

    const int j0 = blockIdx.x * 64;
    const int t0 = blockIdx.y * 64;

    __shared__ __align__(16) float As[8][64];
    __shared__ __align__(16) float Bs[8][64];
    __shared__ int sidx[64];

    const int tid = threadIdx.x;
    if (tid < 64) {
        int t = t0 + tid;
        sidx[tid] = sentence[dir ? (T_LEN - 1 - t) : t];
    }
    __syncthreads();

    const int tx = tid & 15, ty = tid >> 4;
    const int lr = tid >> 2;
    const int le = (tid & 3) * 2;

    float acc[4][4] = {};

    for (int e0 = 0; e0 < EMBD; e0 += 8) {
        const float* arow = embed + (size_t)sidx[lr] * EMBD;
        const float* brow = w_ih + (size_t)(j0 + lr) * EMBD;
        int e = e0 + le;
        As[le][lr]     = (e     < EMBD) ? arow[e]     : 0.f;
        As[le + 1][lr] = (e + 1 < EMBD) ? arow[e + 1] : 0.f;
        Bs[le][lr]     = (e     < EMBD) ? brow[e]     : 0.f;
        Bs[le + 1][lr] = (e + 1 < EMBD) ? brow[e + 1] : 0.f;
        __syncthreads();
#pragma unroll
        for (int kk = 0; kk < 8; kk++) {
            float4 a = *(const float4*)&As[kk][ty * 4];
            float4 b = *(const float4*)&Bs[kk][tx * 4];
            float av[4] = {a.x, a.y, a.z, a.w};
            float bv[4] = {b.x, b.y, b.z, b.w};
#pragma unroll
            for (int i = 0; i < 4; i++)
#pragma unroll
                for (int j = 0; j < 4; j++)
                    acc[i][j] = fmaf(av[i], bv[j], acc[i][j]);
        }
        __syncthreads();
    }

#pragma unroll
    for (int i = 0; i < 4; i++) {
        int t = t0 + ty * 4 + i;
#pragma unroll
        for (int j = 0; j < 4; j++) {
            int jj = j0 + tx * 4 + j;
            g_xproj[dir][t][jj] = acc[i][j] + bi[jj] + bh[jj];
        }
    }
}

// ---------------- K3: persistent BiLSTM, staggered A/B pipeline ----------------
// 64 CTAs, both directions per CTA. Warp w owns h-index hidx=cid*8+w.
// Speculative polls issued one compute-phase before their check: L2 latency
// hidden under the other direction's compute.
__global__ __launch_bounds__(256, 1) void lstm_kernel(
    const float* __restrict__ w_hh_f,
    const float* __restrict__ w_hh_b,
    const float* __restrict__ c0)
{
    const int cid  = blockIdx.x;
    const int tid  = threadIdx.x;
    const int wid  = tid >> 5;
    const int lane = tid & 31;
    const int gate = lane >> 3;
    const int kg   = lane & 7;
    const int hidx = cid * 8 + wid;
    const int row  = gate * HID + hidx;

    // weights for both dirs as packed f32x2 pairs, swizzled by kg
    ulonglong2 wA[16], wB[16];
    {
        const float4* ra = (const float4*)(w_hh_f + (size_t)row * HID + kg * 64);
        const float4* rb = (const float4*)(w_hh_b + (size_t)row * HID + kg * 64);
#pragma unroll
        for (int kk = 0; kk < 16; kk++) {
            float4 a = ra[(kk + kg) & 15];
            float4 b = rb[(kk + kg) & 15];
            wA[kk] = *(ulonglong2*)&a;
            wB[kk] = *(ulonglong2*)&b;
        }
    }

    __shared__ __align__(16) float h_shA[2][HID];
    __shared__ __align__(16) float h_shB[2][HID];

    float cA = (lane == 0) ? c0[hidx]       : 0.f;
    float cB = (lane == 0) ? c0[HID + hidx] : 0.f;
    float xpA = (kg == 0) ? g_xproj[0][0][row] : 0.f;
    float xpB = (kg == 0) ? g_xproj[1][0][row] : 0.f;

    unsigned long long sA0, sA1, sB0, sB1;
    // pre-issue speculative load of A(0) (seeded, will hit)
    LD2_RELAXED(sA0, sA1, g_hpair[0][0] + 2 * tid);

    for (int t = 0; t < T_LEN; t++) {
        const int p = t & 1;
        const unsigned wanted = (unsigned)t;

        // ===== PHASE A =====
        {   // check speculative A(t); retry if not landed
            const unsigned long long* pa = g_hpair[0][p] + 2 * tid;
            while ((unsigned)(sA0 >> 32) != wanted || (unsigned)(sA1 >> 32) != wanted)
                LD2_RELAXED(sA0, sA1, pa);
            h_shA[p][2 * tid]     = __uint_as_float((unsigned)sA0);
            h_shA[p][2 * tid + 1] = __uint_as_float((unsigned)sA1);
        }
        // speculative issue B(t) — checked after computeA
        LD2_RELAXED(sB0, sB1, g_hpair[1][p] + 2 * tid);
        __syncthreads();
        {   // compute direction 0
            unsigned long long acc01 = 0ull, acc23 = 0ull;
            const ulonglong2* hb = (const ulonglong2*)(h_shA[p] + kg * 64);
#pragma unroll
            for (int kk = 0; kk < 16; kk++) {
                ulonglong2 h2 = hb[(kk + kg) & 15];
                FMA_F32X2(acc01, wA[kk].x, h2.x);
                FMA_F32X2(acc23, wA[kk].y, h2.y);
            }
            unsigned lo0, hi0, lo1, hi1;
            asm("mov.b64 {%0,%1}, %2;" : "=r"(lo0), "=r"(hi0) : "l"(acc01));
            asm("mov.b64 {%0,%1}, %2;" : "=r"(lo1), "=r"(hi1) : "l"(acc23));
            float acc = (__uint_as_float(lo0) + __uint_as_float(hi0))
                      + (__uint_as_float(lo1) + __uint_as_float(hi1));
            if (kg == 0) acc += xpA;
            acc += __shfl_xor_sync(0xffffffffu, acc, 4);
            acc += __shfl_xor_sync(0xffffffffu, acc, 2);
            acc += __shfl_xor_sync(0xffffffffu, acc, 1);
            float vf = __shfl_sync(0xffffffffu, acc, 8);
            float vg = __shfl_sync(0xffffffffu, acc, 16);
            float vo = __shfl_sync(0xffffffffu, acc, 24);
            if (lane == 0) {
                float fi = sigm_fast(acc);
                float ff = sigm_fast(vf);
                float fo = sigm_fast(vo);
                cA = ff * cA + fi * tanh_fast(vg);
                float hn = fo * tanh_fast(cA);
                unsigned long long pv = packhf((unsigned)(t + 1), hn);
                asm volatile("st.relaxed.gpu.global.u64 [%0], %1;"
                             :: "l"(g_hpair[0][p ^ 1] + hidx), "l"(pv) : "memory");
                g_hs[0][t][hidx] = hn;
            }
            if (kg == 0 && t + 1 < T_LEN) xpA = g_xproj[0][t + 1][row];
        }

        // ===== PHASE B =====
        {   // check speculative B(t) — L2 latency was hidden under computeA
            const unsigned long long* pb = g_hpair[1][p] + 2 * tid;
            while ((unsigned)(sB0 >> 32) != wanted || (unsigned)(sB1 >> 32) != wanted)
                LD2_RELAXED(sB0, sB1, pb);
            h_shB[p][2 * tid]     = __uint_as_float((unsigned)sB0);
            h_shB[p][2 * tid + 1] = __uint_as_float((unsigned)sB1);
        }
        // speculative issue A(t+1) — checked at start of next iteration
        LD2_RELAXED(sA0, sA1, g_hpair[0][p ^ 1] + 2 * tid);
        __syncthreads();
        {   // compute direction 1
            unsigned long long acc01 = 0ull, acc23 = 0ull;
            const ulonglong2* hb = (const ulonglong2*)(h_shB[p] + kg * 64);
#pragma unroll
            for (int kk = 0; kk < 16; kk++) {
                ulonglong2 h2 = hb[(kk + kg) & 15];
                FMA_F32X2(acc01, wB[kk].x, h2.x);
                FMA_F32X2(acc23, wB[kk].y, h2.y);
            }
            unsigned lo0, hi0, lo1, hi1;
            asm("mov.b64 {%0,%1}, %2;" : "=r"(lo0), "=r"(hi0) : "l"(acc01));
            asm("mov.b64 {%0,%1}, %2;" : "=r"(lo1), "=r"(hi1) : "l"(acc23));
            float acc = (__uint_as_float(lo0) + __uint_as_float(hi0))
                      + (__uint_as_float(lo1) + __uint_as_float(hi1));
            if (kg == 0) acc += xpB;
            acc += __shfl_xor_sync(0xffffffffu, acc, 4);
            acc += __shfl_xor_sync(0xffffffffu, acc, 2);
            acc += __shfl_xor_sync(0xffffffffu, acc, 1);
            float vf = __shfl_sync(0xffffffffu, acc, 8);
            float vg = __shfl_sync(0xffffffffu, acc, 16);
            float vo = __shfl_sync(0xffffffffu, acc, 24);
            if (lane == 0) {
                float fi = sigm_fast(acc);
                float ff = sigm_fast(vf);
                float fo = sigm_fast(vo);
                cB = ff * cB + fi * tanh_fast(vg);
                float hn = fo * tanh_fast(cB);
                unsigned long long pv = packhf((unsigned)(t + 1), hn);
                asm volatile("st.relaxed.gpu.global.u64 [%0], %1;"
                             :: "l"(g_hpair[1][p ^ 1] + hidx), "l"(pv) : "memory");
                g_hs[1][t][hidx] = hn;
            }
            if (kg == 0 && t + 1 < T_LEN) xpB = g_xproj[1][t + 1][row];
        }
    }
}

// ---------------- K4: feats[t,k] = [h_f(t), h_b(t)] . W_tag[k] + b_tag[k] ----------------
__global__ __launch_bounds__(256) void feats_kernel(
    const float* __restrict__ W_tag, const float* __restrict__ b_tag)
{
    const int t = blockIdx.x;
    __shared__ float hsm[2 * HID];
    const int tid = threadIdx.x;
    for (int i = tid; i < HID; i += 256) {
        hsm[i]       = g_hs[0][t][i];
        hsm[HID + i] = g_hs[1][T_LEN - 1 - t][i];
    }
    __syncthreads();
    const int wid = tid >> 5, lane = tid & 31;
    for (int k = wid; k < KTAG; k += 8) {
        const float* wrow = W_tag + (size_t)k * (2 * HID);
        float s = 0.f;
#pragma unroll
        for (int m = 0; m < 32; m++)
            s = fmaf(wrow[m * 32 + lane], hsm[m * 32 + lane], s);
#pragma unroll
        for (int off = 16; off; off >>= 1)
            s += __shfl_xor_sync(0xffffffffu, s, off);
        if (lane == 0) g_feats[t][k] = s + b_tag[k];
    }
}

// ---------------- K5a: per-chunk sequential composition (256 warps) ----------------
__global__ __launch_bounds__(32) void crf_chunk_kernel(const float* __restrict__ trans)
{
    const int c = blockIdx.x;
    const int lane = threadIdx.x;
    __shared__ float Tsm[KTAG][KTAG];
    __shared__ float Mbuf[2][KTAG][KTAG];
    __shared__ float fsm[KTAG];

    for (int i = lane; i < KTAG * KTAG; i += 32)
        Tsm[i / KTAG][i % KTAG] = trans[i];
    __syncwarp();

    if (lane < KTAG) fsm[lane] = g_feats[c * CHUNK][lane];
    __syncwarp();
    for (int e = lane; e < KTAG * KTAG; e += 32)
        Mbuf[0][e / KTAG][e % KTAG] = Tsm[e / KTAG][e % KTAG] + fsm[e / KTAG];
    __syncwarp();

    int cur = 0;
    for (int s = 1; s < CHUNK; s++) {
        if (lane < KTAG) fsm[lane] = g_feats[c * CHUNK + s][lane];
        __syncwarp();
        for (int e = lane; e < KTAG * KTAG; e += 32) {
            int j = e / KTAG, i = e % KTAG;
            float v[KTAG], mx = -3.4e38f;
#pragma unroll
            for (int k = 0; k < KTAG; k++) {
                v[k] = Tsm[j][k] + Mbuf[cur][k][i];
                mx = fmaxf(mx, v[k]);
            }
            float sm = 0.f;
#pragma unroll
            for (int k = 0; k < KTAG; k++) sm += __expf(v[k] - mx);
            Mbuf[cur ^ 1][j][i] = fsm[j] + mx + __logf(sm);
        }
        __syncwarp();
        cur ^= 1;
    }
    for (int e = lane; e < KTAG * KTAG; e += 32)
        g_tree[0][c][e / KTAG][e % KTAG] = Mbuf[cur][e / KTAG][e % KTAG];
}

// ---------------- K5b: tree combine. out[b] = in[2b+1] (.) in[2b] ----------------
__global__ __launch_bounds__(32) void crf_combine_kernel(int s)
{
    const int b = blockIdx.x;
    const int lane = threadIdx.x;
    const float (*in)[KTAG][KTAG]  = g_tree[s & 1];
    float (*out)[KTAG][KTAG]       = g_tree[(s & 1) ^ 1];
    __shared__ float Lo[KTAG][KTAG], Hi[KTAG][KTAG];
    for (int i = lane; i < KTAG * KTAG; i += 32) {
        Lo[i / KTAG][i % KTAG] = in[2 * b][i / KTAG][i % KTAG];
        Hi[i / KTAG][i % KTAG] = in[2 * b + 1][i / KTAG][i % KTAG];
    }
    __syncwarp();
    for (int e = lane; e < KTAG * KTAG; e += 32) {
        int j = e / KTAG, i = e % KTAG;
        float v[KTAG], mx = -3.4e38f;
#pragma unroll
        for (int k = 0; k < KTAG; k++) {
            v[k] = Hi[j][k] + Lo[k][i];
            mx = fmaxf(mx, v[k]);
        }
        float sm = 0.f;
#pragma unroll
        for (int k = 0; k < KTAG; k++) sm += __expf(v[k] - mx);
        out[b][j][i] = mx + __logf(sm);
    }
}

// ---------------- K5c: final score = forward - gold ----------------
__global__ void crf_final_kernel(const int* __restrict__ tags,
                                 const float* __restrict__ trans,
                                 float* __restrict__ out)
{
    __shared__ float partial[128];
    const int tid = threadIdx.x;

    float loc = 0.f;
    for (int t = tid; t < T_LEN; t += 128) {
        int tg = tags[t];
        int pv = t ? tags[t - 1] : START_TAG;
        loc += trans[tg * KTAG + pv] + g_feats[t][tg];
    }
    partial[tid] = loc;
    __syncthreads();

    if (tid == 0) {
        float gold = trans[STOP_TAG * KTAG + tags[T_LEN - 1]];
        for (int i = 0; i < 128; i++) gold += partial[i];

        const float (*C)[KTAG] = g_tree[0][0];
        float alpha[KTAG];
        for (int j = 0; j < KTAG; j++) {
            float mx = -3.4e38f, v[KTAG];
            for (int i = 0; i < KTAG; i++) {
                v[i] = C[j][i] + ((i == START_TAG) ? 0.f : NEGV);
                mx = fmaxf(mx, v[i]);
            }
            float sm = 0.f;
            for (int i = 0; i < KTAG; i++) sm += __expf(v[i] - mx);
            alpha[j] = mx + __logf(sm);
        }
        float mx = -3.4e38f;
        for (int j = 0; j < KTAG; j++)
            mx = fmaxf(mx, alpha[j] + trans[STOP_TAG * KTAG + j]);
        float sm = 0.f;
        for (int j = 0; j < KTAG; j++)
            sm += __expf(alpha[j] + trans[STOP_TAG * KTAG + j] - mx);
        out[0] = (mx + __logf(sm)) - gold;
    }
}

// ---------------- launch ----------------
extern "C" void kernel_launch(void* const* d_in, const int* in_sizes, int n_in,
                              void* d_out, int out_size)
{
    const int*   sentence = (const int*)d_in[0];
    const int*   tags     = (const int*)d_in[1];
    const float* embed    = (const float*)d_in[2];
    const float* w_ih_f   = (const float*)d_in[3];
    const float* w_hh_f   = (const float*)d_in[4];
    const float* b_ih_f   = (const float*)d_in[5];
    const float* b_hh_f   = (const float*)d_in[6];
    const float* w_ih_b   = (const float*)d_in[7];
    const float* w_hh_b   = (const float*)d_in[8];
    const float* b_ih_b   = (const float*)d_in[9];
    const float* b_hh_b   = (const float*)d_in[10];
    const float* h0       = (const float*)d_in[11];
    const float* c0       = (const float*)d_in[12];
    const float* W_tag    = (const float*)d_in[13];
    const float* b_tag    = (const float*)d_in[14];
    const float* trans    = (const float*)d_in[15];

    init_kernel<<<1, 1024>>>(h0);

    dim3 g1((4 * HID) / 64, T_LEN / 64, 2);
    xproj_kernel<<<g1, 256>>>(sentence, embed,
                              w_ih_f, b_ih_f, b_hh_f,
                              w_ih_b, b_ih_b, b_hh_b);

    lstm_kernel<<<64, 256>>>(w_hh_f, w_hh_b, c0);

    feats_kernel<<<T_LEN, 256>>>(W_tag, b_tag);

    crf_chunk_kernel<<<NCHUNK, 32>>>(trans);
    for (int s = 0; s < 8; s++)
        crf_combine_kernel<<<(NCHUNK / 2) >> s, 32>>>(s);
    crf_final_kernel<<<1, 128>>>(tags, trans, (float*)d_out);
}

// round 6
// speedup vs baseline: 1.2948x; 1.2948x over previous
#include <cuda_runtime.h>
#include <cuda_bf16.h>
#include <cstdint>
#include <cstddef>

#define T_LEN 4096
#define EMBD  300
#define HID   512
#define KTAG  20
#define START_TAG 18
#define STOP_TAG  19
#define NEGV  (-10000.0f)
#define CHUNK 16
#define NCHUNK (T_LEN / CHUNK)   // 256

// ---------------- scratch (static device globals; no allocation) ----------------
__device__ float              g_xproj[2][T_LEN][4 * HID];  // 64 MB
__device__ float              g_hs[2][T_LEN][HID];         // 16 MB
__device__ float              g_feats[T_LEN][KTAG];
__device__ unsigned long long g_hpair[2][2][HID];          // [dir][parity][h]: {tag|bits}
__device__ float              g_tree[2][NCHUNK][KTAG][KTAG];

__device__ __forceinline__ unsigned long long packhf(unsigned tag, float v) {
    return ((unsigned long long)tag << 32) | (unsigned long long)__float_as_uint(v);
}
__device__ __forceinline__ float tanh_fast(float x) {
    return 1.f - 2.f / (__expf(2.f * x) + 1.f);
}
__device__ __forceinline__ float sigm_fast(float x) {
    return 1.f / (1.f + __expf(-x));
}

// ---------------- init: seed h0 pairs (tag 0), poison other parity ----------------
__global__ void init_kernel(const float* __restrict__ h0) {
    int tid = threadIdx.x;                // 1024 threads
    int dir = tid >> 9, i = tid & 511;
    g_hpair[dir][0][i] = packhf(0u, h0[dir * HID + i]);
    g_hpair[dir][1][i] = packhf(0x7fffffffu, 0.f);
}

// ---------------- K1: x_proj = emb(gather) @ w_ih^T + b_ih + b_hh ----------------
__global__ __launch_bounds__(256) void xproj_kernel(
    const int*   __restrict__ sentence,
    const float* __restrict__ embed,
    const float* __restrict__ w_ih_f, const float* __restrict__ b_ih_f, const float* __restrict__ b_hh_f,
    const float* __restrict__ w_ih_b, const float* __restrict__ b_ih_b, const float* __restrict__ b_hh_b)
{
    const int dir = blockIdx.z;
    const float* __restrict__ w_ih = dir ? w_ih_b : w_ih_f;
    const float* __restrict__ bi   = dir ? b_ih_b : b_ih_f;
    const float* __restrict__ bh   = dir ? b_hh_b : b_hh_f;

    const int j0 = blockIdx.x * 64;
    const int t0 = blockIdx.y * 64;

    __shared__ __align__(16) float As[8][64];
    __shared__ __align__(16) float Bs[8][64];
    __shared__ int sidx[64];

    const int tid = threadIdx.x;
    if (tid < 64) {
        int t = t0 + tid;
        sidx[tid] = sentence[dir ? (T_LEN - 1 - t) : t];
    }
    __syncthreads();

    const int tx = tid & 15, ty = tid >> 4;
    const int lr = tid >> 2;
    const int le = (tid & 3) * 2;

    float acc[4][4] = {};

    for (int e0 = 0; e0 < EMBD; e0 += 8) {
        const float* arow = embed + (size_t)sidx[lr] * EMBD;
        const float* brow = w_ih + (size_t)(j0 + lr) * EMBD;
        int e = e0 + le;
        As[le][lr]     = (e     < EMBD) ? arow[e]     : 0.f;
        As[le + 1][lr] = (e + 1 < EMBD) ? arow[e + 1] : 0.f;
        Bs[le][lr]     = (e     < EMBD) ? brow[e]     : 0.f;
        Bs[le + 1][lr] = (e + 1 < EMBD) ? brow[e + 1] : 0.f;
        __syncthreads();
#pragma unroll
        for (int kk = 0; kk < 8; kk++) {
            float4 a = *(const float4*)&As[kk][ty * 4];
            float4 b = *(const float4*)&Bs[kk][tx * 4];
            float av[4] = {a.x, a.y, a.z, a.w};
            float bv[4] = {b.x, b.y, b.z, b.w};
#pragma unroll
            for (int i = 0; i < 4; i++)
#pragma unroll
                for (int j = 0; j < 4; j++)
                    acc[i][j] = fmaf(av[i], bv[j], acc[i][j]);
        }
        __syncthreads();
    }

#pragma unroll
    for (int i = 0; i < 4; i++) {
        int t = t0 + ty * 4 + i;
#pragma unroll
        for (int j = 0; j < 4; j++) {
            int jj = j0 + tx * 4 + j;
            g_xproj[dir][t][jj] = acc[i][j] + bi[jj] + bh[jj];
        }
    }
}

// ---------------- K3: persistent BiLSTM (disjoint dirs, low-LDS tiling) ----------------
// 128 CTAs (64/dir). Warp w of CTA owns h-index hidx = cid*8+w (ALL 4 gate rows).
// Lane l covers k in {4l..4l+3} + {128,256,384} offsets: 16 h values, 64 FMAs,
// accumulating all 4 gates. LDS = 16KB/step/CTA (4x less than R3).
__global__ __launch_bounds__(256, 1) void lstm_kernel(
    const float* __restrict__ w_hh_f,
    const float* __restrict__ w_hh_b,
    const float* __restrict__ c0)
{
    const int dir  = blockIdx.x >> 6;
    const int cid  = blockIdx.x & 63;
    const float* __restrict__ w_hh = dir ? w_hh_b : w_hh_f;

    const int tid  = threadIdx.x;
    const int wid  = tid >> 5;
    const int lane = tid & 31;
    const int hidx = cid * 8 + wid;

    // weights: w4[g][j] = w_hh[g*512+hidx][j*128 + 4*lane .. +3]
    float4 w4[4][4];
#pragma unroll
    for (int g = 0; g < 4; g++) {
        const float* wr = w_hh + (size_t)(g * HID + hidx) * HID + 4 * lane;
#pragma unroll
        for (int j = 0; j < 4; j++)
            w4[g][j] = *(const float4*)(wr + j * 128);
    }

    __shared__ __align__(16) float h_sh[2][HID];

    float creg = (lane == 0) ? c0[dir * HID + hidx] : 0.f;
    float xp   = (lane < 4) ? g_xproj[dir][0][lane * HID + hidx] : 0.f;

    const unsigned long long* rd0 = g_hpair[dir][0];
    const unsigned long long* rd1 = g_hpair[dir][1];

    for (int t = 0; t < T_LEN; t++) {
        const int p = t & 1;
        // --- poll own 2 pairs of h(t), stash to smem ---
        {
            const unsigned long long* pa = (p ? rd1 : rd0) + 2 * tid;
            const unsigned wanted = (unsigned)t;
            unsigned long long a, b;
            do {
                asm volatile("ld.relaxed.gpu.global.v2.u64 {%0,%1}, [%2];"
                             : "=l"(a), "=l"(b) : "l"(pa) : "memory");
            } while ((unsigned)(a >> 32) != wanted || (unsigned)(b >> 32) != wanted);
            h_sh[p][2 * tid]     = __uint_as_float((unsigned)a);
            h_sh[p][2 * tid + 1] = __uint_as_float((unsigned)b);
        }
        __syncthreads();

        // --- matvec: 16 h values per lane feed all 4 gate rows ---
        const float* hb = h_sh[p] + 4 * lane;
        float4 h0 = *(const float4*)(hb);
        float4 h1 = *(const float4*)(hb + 128);
        float4 h2 = *(const float4*)(hb + 256);
        float4 h3 = *(const float4*)(hb + 384);

        float acc0, acc1, acc2, acc3;
        {
            float4 h[4] = {h0, h1, h2, h3};
            float a[4];
#pragma unroll
            for (int g = 0; g < 4; g++) {
                float s0 = 0.f, s1 = 0.f;
#pragma unroll
                for (int j = 0; j < 4; j++) {
                    s0 = fmaf(w4[g][j].x, h[j].x, s0);
                    s1 = fmaf(w4[g][j].y, h[j].y, s1);
                    s0 = fmaf(w4[g][j].z, h[j].z, s0);
                    s1 = fmaf(w4[g][j].w, h[j].w, s1);
                }
                a[g] = s0 + s1;
            }
            acc0 = a[0]; acc1 = a[1]; acc2 = a[2]; acc3 = a[3];
        }
        // butterfly reduce all 4 gate sums across the warp (4-way ILP)
#pragma unroll
        for (int off = 16; off; off >>= 1) {
            acc0 += __shfl_xor_sync(0xffffffffu, acc0, off);
            acc1 += __shfl_xor_sync(0xffffffffu, acc1, off);
            acc2 += __shfl_xor_sync(0xffffffffu, acc2, off);
            acc3 += __shfl_xor_sync(0xffffffffu, acc3, off);
        }

        // lanes 0..3 apply their gate's nonlinearity in parallel
        float nl = 0.f;
        if (lane < 4) {
            float v = (lane == 0) ? acc0 : (lane == 1) ? acc1
                    : (lane == 2) ? acc2 : acc3;
            v += xp;
            nl = (lane == 2) ? tanh_fast(v) : sigm_fast(v);
        }
        float ff = __shfl_sync(0xffffffffu, nl, 1);
        float tg = __shfl_sync(0xffffffffu, nl, 2);
        float fo = __shfl_sync(0xffffffffu, nl, 3);
        if (lane == 0) {
            creg = ff * creg + nl * tg;          // nl = fi on lane 0
            float hn = fo * tanh_fast(creg);
            unsigned long long pv = packhf((unsigned)(t + 1), hn);
            asm volatile("st.relaxed.gpu.global.u64 [%0], %1;"
                         :: "l"((p ? rd0 : rd1) + hidx), "l"(pv) : "memory");
            g_hs[dir][t][hidx] = hn;
        }
        if (lane < 4 && t + 1 < T_LEN)
            xp = g_xproj[dir][t + 1][lane * HID + hidx];   // prefetch
        // no trailing barrier: next stash targets the other parity buffer.
    }
}

// ---------------- K4: feats[t,k] = [h_f(t), h_b(t)] . W_tag[k] + b_tag[k] ----------------
__global__ __launch_bounds__(256) void feats_kernel(
    const float* __restrict__ W_tag, const float* __restrict__ b_tag)
{
    const int t = blockIdx.x;
    __shared__ float hsm[2 * HID];
    const int tid = threadIdx.x;
    for (int i = tid; i < HID; i += 256) {
        hsm[i]       = g_hs[0][t][i];
        hsm[HID + i] = g_hs[1][T_LEN - 1 - t][i];
    }
    __syncthreads();
    const int wid = tid >> 5, lane = tid & 31;
    for (int k = wid; k < KTAG; k += 8) {
        const float* wrow = W_tag + (size_t)k * (2 * HID);
        float s = 0.f;
#pragma unroll
        for (int m = 0; m < 32; m++)
            s = fmaf(wrow[m * 32 + lane], hsm[m * 32 + lane], s);
#pragma unroll
        for (int off = 16; off; off >>= 1)
            s += __shfl_xor_sync(0xffffffffu, s, off);
        if (lane == 0) g_feats[t][k] = s + b_tag[k];
    }
}

// ---------------- K5a: per-chunk sequential composition (256 warps) ----------------
__global__ __launch_bounds__(32) void crf_chunk_kernel(const float* __restrict__ trans)
{
    const int c = blockIdx.x;
    const int lane = threadIdx.x;
    __shared__ float Tsm[KTAG][KTAG];
    __shared__ float Mbuf[2][KTAG][KTAG];
    __shared__ float fsm[KTAG];

    for (int i = lane; i < KTAG * KTAG; i += 32)
        Tsm[i / KTAG][i % KTAG] = trans[i];
    __syncwarp();

    if (lane < KTAG) fsm[lane] = g_feats[c * CHUNK][lane];
    __syncwarp();
    for (int e = lane; e < KTAG * KTAG; e += 32)
        Mbuf[0][e / KTAG][e % KTAG] = Tsm[e / KTAG][e % KTAG] + fsm[e / KTAG];
    __syncwarp();

    int cur = 0;
    for (int s = 1; s < CHUNK; s++) {
        if (lane < KTAG) fsm[lane] = g_feats[c * CHUNK + s][lane];
        __syncwarp();
        for (int e = lane; e < KTAG * KTAG; e += 32) {
            int j = e / KTAG, i = e % KTAG;
            float v[KTAG], mx = -3.4e38f;
#pragma unroll
            for (int k = 0; k < KTAG; k++) {
                v[k] = Tsm[j][k] + Mbuf[cur][k][i];
                mx = fmaxf(mx, v[k]);
            }
            float sm = 0.f;
#pragma unroll
            for (int k = 0; k < KTAG; k++) sm += __expf(v[k] - mx);
            Mbuf[cur ^ 1][j][i] = fsm[j] + mx + __logf(sm);
        }
        __syncwarp();
        cur ^= 1;
    }
    for (int e = lane; e < KTAG * KTAG; e += 32)
        g_tree[0][c][e / KTAG][e % KTAG] = Mbuf[cur][e / KTAG][e % KTAG];
}

// ---------------- K5b: tree combine. out[b] = in[2b+1] (.) in[2b] ----------------
__global__ __launch_bounds__(32) void crf_combine_kernel(int s)
{
    const int b = blockIdx.x;
    const int lane = threadIdx.x;
    const float (*in)[KTAG][KTAG]  = g_tree[s & 1];
    float (*out)[KTAG][KTAG]       = g_tree[(s & 1) ^ 1];
    __shared__ float Lo[KTAG][KTAG], Hi[KTAG][KTAG];
    for (int i = lane; i < KTAG * KTAG; i += 32) {
        Lo[i / KTAG][i % KTAG] = in[2 * b][i / KTAG][i % KTAG];
        Hi[i / KTAG][i % KTAG] = in[2 * b + 1][i / KTAG][i % KTAG];
    }
    __syncwarp();
    for (int e = lane; e < KTAG * KTAG; e += 32) {
        int j = e / KTAG, i = e % KTAG;
        float v[KTAG], mx = -3.4e38f;
#pragma unroll
        for (int k = 0; k < KTAG; k++) {
            v[k] = Hi[j][k] + Lo[k][i];
            mx = fmaxf(mx, v[k]);
        }
        float sm = 0.f;
#pragma unroll
        for (int k = 0; k < KTAG; k++) sm += __expf(v[k] - mx);
        out[b][j][i] = mx + __logf(sm);
    }
}

// ---------------- K5c: final score = forward - gold ----------------
__global__ void crf_final_kernel(const int* __restrict__ tags,
                                 const float* __restrict__ trans,
                                 float* __restrict__ out)
{
    __shared__ float partial[128];
    const int tid = threadIdx.x;

    float loc = 0.f;
    for (int t = tid; t < T_LEN; t += 128) {
        int tg = tags[t];
        int pv = t ? tags[t - 1] : START_TAG;
        loc += trans[tg * KTAG + pv] + g_feats[t][tg];
    }
    partial[tid] = loc;
    __syncthreads();

    if (tid == 0) {
        float gold = trans[STOP_TAG * KTAG + tags[T_LEN - 1]];
        for (int i = 0; i < 128; i++) gold += partial[i];

        const float (*C)[KTAG] = g_tree[0][0];
        float alpha[KTAG];
        for (int j = 0; j < KTAG; j++) {
            float mx = -3.4e38f, v[KTAG];
            for (int i = 0; i < KTAG; i++) {
                v[i] = C[j][i] + ((i == START_TAG) ? 0.f : NEGV);
                mx = fmaxf(mx, v[i]);
            }
            float sm = 0.f;
            for (int i = 0; i < KTAG; i++) sm += __expf(v[i] - mx);
            alpha[j] = mx + __logf(sm);
        }
        float mx = -3.4e38f;
        for (int j = 0; j < KTAG; j++)
            mx = fmaxf(mx, alpha[j] + trans[STOP_TAG * KTAG + j]);
        float sm = 0.f;
        for (int j = 0; j < KTAG; j++)
            sm += __expf(alpha[j] + trans[STOP_TAG * KTAG + j] - mx);
        out[0] = (mx + __logf(sm)) - gold;
    }
}

// ---------------- launch ----------------
extern "C" void kernel_launch(void* const* d_in, const int* in_sizes, int n_in,
                              void* d_out, int out_size)
{
    const int*   sentence = (const int*)d_in[0];
    const int*   tags     = (const int*)d_in[1];
    const float* embed    = (const float*)d_in[2];
    const float* w_ih_f   = (const float*)d_in[3];
    const float* w_hh_f   = (const float*)d_in[4];
    const float* b_ih_f   = (const float*)d_in[5];
    const float* b_hh_f   = (const float*)d_in[6];
    const float* w_ih_b   = (const float*)d_in[7];
    const float* w_hh_b   = (const float*)d_in[8];
    const float* b_ih_b   = (const float*)d_in[9];
    const float* b_hh_b   = (const float*)d_in[10];
    const float* h0       = (const float*)d_in[11];
    const float* c0       = (const float*)d_in[12];
    const float* W_tag    = (const float*)d_in[13];
    const float* b_tag    = (const float*)d_in[14];
    const float* trans    = (const float*)d_in[15];

    init_kernel<<<1, 1024>>>(h0);

    dim3 g1((4 * HID) / 64, T_LEN / 64, 2);
    xproj_kernel<<<g1, 256>>>(sentence, embed,
                              w_ih_f, b_ih_f, b_hh_f,
                              w_ih_b, b_ih_b, b_hh_b);

    lstm_kernel<<<128, 256>>>(w_hh_f, w_hh_b, c0);

    feats_kernel<<<T_LEN, 256>>>(W_tag, b_tag);

    crf_chunk_kernel<<<NCHUNK, 32>>>(trans);
    for (int s = 0; s < 8; s++)
        crf_combine_kernel<<<(NCHUNK / 2) >> s, 32>>>(s);
    crf_final_kernel<<<1, 128>>>(tags, trans, (float*)d_out);
}